// round 14
// baseline (speedup 1.0000x reference)
#include <cuda_runtime.h>
#include <cuda_bf16.h>
#include <math.h>

#define S_LEN 512
#define BATCH 256
#define DIN   256
#define HID   512
#define HIST  2048
#define NB    128
#define SW_BYTES (144*1280)                 /* 184320: 24kc*3p*2term tiles of 16x40 shorts */
#define SA_STAGE 5120                       /* 64 rows x 40 shorts x 2B */
#define SMEM_DYN (SW_BYTES + 4*SA_STAGE)    /* 204800 */

// ---------------- device scratch ----------------
// x image: [t][rt4][kc8][row64][kl32] bf16 (hi only)
__device__ unsigned short d_xbf[(size_t)S_LEN*4*8*2048];     // 64MB
// h image: [par2][rt4][kc16][row64][kl32]
__device__ unsigned short d_hbf[2*4*16*2048];
// W image: [ct32][kc24][p3][term2][j16][kl32]  (hi+lo)
__device__ unsigned short d_wbf[32*24*3*2*512];
__device__ float d_h[2][BATCH*HID];
__device__ float d_g[BATCH*HIST];
__device__ float d_alpha[BATCH*HIST];
__device__ float d_sig[BATCH*DIN];
__device__ float d_mu[BATCH*DIN];
__device__ float d_inv_sigma[BATCH*DIN];
__device__ float d_logdet[BATCH];
__device__ unsigned int g_arrive;
__device__ volatile unsigned int g_release;

__global__ void reset_barrier_kernel() { g_arrive = 0; g_release = 0; }

// ---------------- PTX helpers ----------------
__device__ __forceinline__ unsigned smem_u32(const void* p){
    unsigned a; asm("{ .reg .u64 t; cvta.to.shared.u64 t, %1; cvt.u32.u64 %0, t; }":"=r"(a):"l"(p)); return a;
}
__device__ __forceinline__ void ldsm4(unsigned* r, unsigned addr){
    asm volatile("ldmatrix.sync.aligned.m8n8.x4.shared.b16 {%0,%1,%2,%3}, [%4];"
        : "=r"(r[0]),"=r"(r[1]),"=r"(r[2]),"=r"(r[3]) : "r"(addr));
}
__device__ __forceinline__ void mma16816(float* c, const unsigned* a, unsigned b0, unsigned b1){
    asm volatile("mma.sync.aligned.m16n8k16.row.col.f32.bf16.bf16.f32 "
        "{%0,%1,%2,%3}, {%4,%5,%6,%7}, {%8,%9}, {%0,%1,%2,%3};"
        : "+f"(c[0]),"+f"(c[1]),"+f"(c[2]),"+f"(c[3])
        : "r"(a[0]),"r"(a[1]),"r"(a[2]),"r"(a[3]), "r"(b0),"r"(b1));
}
__device__ __forceinline__ void cpasync16(unsigned s, const void* g){
    asm volatile("cp.async.cg.shared.global [%0], [%1], 16;" :: "r"(s), "l"(g));
}
__device__ __forceinline__ void cpcommit(){ asm volatile("cp.async.commit_group;"); }
__device__ __forceinline__ void cpwait2(){ asm volatile("cp.async.wait_group 2;" ::: "memory"); }
__device__ __forceinline__ void cpwait1(){ asm volatile("cp.async.wait_group 1;" ::: "memory"); }
__device__ __forceinline__ void cpwait0(){ asm volatile("cp.async.wait_group 0;" ::: "memory"); }
__device__ __forceinline__ float sigm(float x){ return 1.f/(1.f+expf(-x)); }

// ---------------- packing ----------------
__global__ __launch_bounds__(256) void pack_x_kernel(const float* __restrict__ x){
    unsigned idx = blockIdx.x*256u + threadIdx.x;
    int kl=idx&31, row=(idx>>5)&63, kc=(idx>>11)&7, rt=(idx>>14)&3, t=idx>>16;
    float v = x[((size_t)t*256 + rt*64 + row)*256 + kc*32 + kl];
    __nv_bfloat16 h = __float2bfloat16(v);
    d_xbf[idx] = *(unsigned short*)&h;
}
__global__ __launch_bounds__(256) void pack_h0_kernel(const float* __restrict__ hidden){
    unsigned idx = blockIdx.x*256u + threadIdx.x;
    int kl=idx&31, row=(idx>>5)&63, kc8=(idx>>11)&15, rt=idx>>15;
    float v = hidden[(size_t)(rt*64+row)*512 + kc8*32 + kl];
    __nv_bfloat16 h = __float2bfloat16(v);
    d_hbf[((size_t)(0*4+rt)*16 + kc8)*2048 + row*32 + kl] = *(unsigned short*)&h;
    d_h[0][(size_t)(rt*64+row)*512 + kc8*32 + kl] = v;
}
__global__ __launch_bounds__(256) void pack_w_kernel(const float* __restrict__ w_ih,
                                                     const float* __restrict__ w_hh){
    unsigned idx = blockIdx.x*256u + threadIdx.x;
    int kl = idx&31, j = (idx>>5)&15;
    int g = idx>>9;
    int p = g%3, kc = (g/3)%24, ct = g/72;
    int kg = kc*32 + kl;
    float w;
    if (p == 0){ int r = ct*16+j;        w = (kg<256)? w_ih[r*256+kg] : w_hh[r*512+kg-256]; }
    else if(p==1){ int r = 512+ct*16+j;  w = (kg<256)? w_ih[r*256+kg] : w_hh[r*512+kg-256]; }
    else { int r = 1024+ct*16+j;
           w = (kc<8)? w_ih[r*256+kg] : w_hh[r*512+kg-256]; }
    __nv_bfloat16 h = __float2bfloat16(w);
    __nv_bfloat16 l = __float2bfloat16(w - __bfloat162float(h));
    size_t base = (size_t)(ct*24+kc)*3072 + (p*2)*512 + j*32 + kl;
    d_wbf[base]       = *(unsigned short*)&h;
    d_wbf[base + 512] = *(unsigned short*)&l;
}

// ---------------- persistent HMMA GRU (weights in smem, 8 warps N-split) ----------------
__device__ __forceinline__ void grid_barrier(unsigned gen){
    __threadfence();
    __syncthreads();
    if(threadIdx.x==0){
        unsigned prev = atomicAdd(&g_arrive, 1u);
        if(prev == NB-1){ g_arrive = 0; __threadfence(); g_release = gen; }
        else { while(g_release < gen) {} __threadfence(); }
    }
    __syncthreads();
}

__device__ __forceinline__ void issue_chunk(int t,int par,int rt,int kc,int stage,
                                            unsigned sAb,int tid){
    const unsigned short* s0 = (kc<8)
        ? d_xbf + ((size_t)(t*4+rt)*8+kc)*2048
        : d_hbf + ((size_t)(par*4+rt)*16+(kc-8))*2048;
    unsigned db = sAb + (unsigned)stage*SA_STAGE;
    int row = tid>>2, q = tid&3;                   // 256 threads -> 4KB
    cpasync16(db + 2u*(unsigned)(row*40 + q*8), s0 + row*32 + q*8);
}

__global__ __launch_bounds__(256,1) void gru_hmma(){
    extern __shared__ __align__(16) unsigned short sm[];
    const int tid = threadIdx.x, lane = tid&31, w = tid>>5;
    const int rw = w&3, nbs = w>>2;                // row quarter, col half
    const int bid = blockIdx.x, rt = bid>>5, ct = bid&31;
    const unsigned sWb = smem_u32(sm);
    const unsigned sAb = sWb + SW_BYTES;
    const int sub8 = lane>>3;
    const unsigned laneoff = 2u*(unsigned)((((lane&7)+((sub8&1)<<3))*40) + ((sub8>>1)<<3));

    // one-time weight preload (all 24 kc chunks, hi+lo, 3 panels)
    {
        const unsigned short* wsrc = d_wbf + (size_t)ct*24*3072;
        for(int i=tid; i<9216; i+=256){            // 16B units
            int tile = i>>6, r2 = i&63, j = r2>>2, q = r2&3;
            cpasync16(sWb + (unsigned)(tile*1280) + 2u*(unsigned)(j*40+q*8),
                      wsrc + tile*512 + j*32 + q*8);
        }
        cpcommit(); cpwait0(); __syncthreads();
    }

    // prologue: chunks 0..2 of step 0
    issue_chunk(0,0,rt,0,0,sAb,tid); cpcommit();
    issue_chunk(0,0,rt,1,1,sAb,tid); cpcommit();
    issue_chunk(0,0,rt,2,2,sAb,tid); cpcommit();

    const int grow0 = rt*64 + rw*16 + (lane>>2);
    const int gcol  = ct*16 + nbs*8 + 2*(lane&3);
    const int klb   = (ct&1)*16 + nbs*8 + 2*(lane&3);
    const int rowl0 = rw*16 + (lane>>2);

    for(int t=0; t<S_LEN; ++t){
        const int par = t&1;
        float accR[4], accZ[4], accI[4], accH[4];
#pragma unroll
        for(int i=0;i<4;i++){ accR[i]=0.f; accZ[i]=0.f; accI[i]=0.f; accH[i]=0.f; }

        for(int kc=0; kc<24; ++kc){
            if(kc<22) cpwait2(); else if(kc==22) cpwait1(); else cpwait0();
            __syncthreads();
            if(kc<21){ issue_chunk(t,par,rt,kc+3,(kc+3)&3,sAb,tid); cpcommit(); }

            const int stage = kc&3;
            unsigned aAddr = sAb + (unsigned)stage*SA_STAGE + (unsigned)(rw*1280) + laneoff;
            float* accN = (kc<8)? accI : accH;
#pragma unroll
            for(int ks=0; ks<2; ks++){
                unsigned ko = (unsigned)(ks*32);
                unsigned ah[4];
                ldsm4(ah, aAddr + ko);
#pragma unroll
                for(int p=0;p<3;p++){
                    unsigned bh[4], bl[4];
                    unsigned tb = sWb + (unsigned)((kc*6 + p*2)*1280);
                    ldsm4(bh, tb + laneoff + ko);
                    ldsm4(bl, tb + 1280u + laneoff + ko);
                    float* acc = (p==0)? accR : (p==1)? accZ : accN;
                    mma16816(acc, ah, bh[0+nbs], bh[2+nbs]);
                    mma16816(acc, ah, bl[0+nbs], bl[2+nbs]);
                }
            }
        }

        // ---- fused gate epilogue (8-warp mapping verified in R13) ----
        const float* hprevB = d_h[par];
        float* houtB = d_h[par^1];
        const size_t imgB = (((size_t)(par^1)*4 + rt)*16 + (ct>>1))*2048;
#pragma unroll
        for(int rh=0; rh<2; rh++){
            int f = rh*2;
            int grow = grow0 + rh*8;
            float2 hp = *(const float2*)&hprevB[(size_t)grow*512 + gcol];
            float r0 = sigm(accR[f]),   r1 = sigm(accR[f+1]);
            float z0 = sigm(accZ[f]),   z1 = sigm(accZ[f+1]);
            float n0 = tanhf(accI[f]   + r0*accH[f]);
            float n1 = tanhf(accI[f+1] + r1*accH[f+1]);
            float h0 = (1.f-z0)*n0 + z0*hp.x;
            float h1 = (1.f-z1)*n1 + z1*hp.y;
            *(float2*)&houtB[(size_t)grow*512 + gcol] = make_float2(h0,h1);
            __nv_bfloat16 bh0=__float2bfloat16(h0), bh1=__float2bfloat16(h1);
            *(unsigned*)&d_hbf[imgB + (size_t)(rowl0 + rh*8)*32 + klb] =
                (unsigned)*(unsigned short*)&bh0 | ((unsigned)*(unsigned short*)&bh1 << 16);
        }

        // pre-issue next step's x chunks (0..2) — independent of h
        if(t+1 < S_LEN){
            issue_chunk(t+1,par^1,rt,0,0,sAb,tid); cpcommit();
            issue_chunk(t+1,par^1,rt,1,1,sAb,tid); cpcommit();
            issue_chunk(t+1,par^1,rt,2,2,sAb,tid); cpcommit();
        }
        grid_barrier((unsigned)(t+1));
    }
}

// ---------------- tail: generic tiled GEMM ----------------
template <int TRANSB>
__global__ __launch_bounds__(128) void gemm_tile_kernel(
        const float* __restrict__ A, int lda, const float* __restrict__ Bm, int ldb,
        float* __restrict__ C, int ldc, int K, int colTiles){
    int bid=blockIdx.x, rt=bid/colTiles, ct=bid%colTiles;
    int row0=rt*32, col0=ct*64;
    __shared__ __align__(16) float sA[16][36];
    __shared__ __align__(16) float sB[16][68];
    int tid=threadIdx.x, tr=tid>>4, tc=tid&15;
    float acc[4][4];
#pragma unroll
    for(int i=0;i<4;i++)
#pragma unroll
        for(int j=0;j<4;j++) acc[i][j]=0.f;
    for(int kk0=0;kk0<K;kk0+=16){
#pragma unroll
        for(int it=0;it<4;it++){ int idx=tid+it*128; int k=idx&15, r=idx>>4;
            sA[k][r]=A[(size_t)(row0+r)*lda+kk0+k]; }
        if(TRANSB){
#pragma unroll
            for(int it=0;it<8;it++){ int idx=tid+it*128; int k=idx&15, j=idx>>4;
                sB[k][j]=Bm[(size_t)(col0+j)*ldb+kk0+k]; }
        } else {
#pragma unroll
            for(int it=0;it<8;it++){ int idx=tid+it*128; int j=idx&63, k=idx>>6;
                sB[k][j]=Bm[(size_t)(kk0+k)*ldb+col0+j]; }
        }
        __syncthreads();
#pragma unroll
        for(int k=0;k<16;k++){
            float4 av=*(const float4*)&sA[k][tr<<2];
            float4 bv=*(const float4*)&sB[k][tc<<2];
            float a[4]={av.x,av.y,av.z,av.w}, b[4]={bv.x,bv.y,bv.z,bv.w};
#pragma unroll
            for(int i=0;i<4;i++)
#pragma unroll
                for(int j=0;j<4;j++) acc[i][j]+=a[i]*b[j];
        }
        __syncthreads();
    }
#pragma unroll
    for(int i=0;i<4;i++){
        float4 v=make_float4(acc[i][0],acc[i][1],acc[i][2],acc[i][3]);
        *(float4*)&C[(size_t)(row0+(tr<<2)+i)*ldc+col0+(tc<<2)]=v;
    }
}

__global__ __launch_bounds__(256) void softmax_kernel(){
    int b=blockIdx.x;
    const float* L=d_g+(size_t)b*HIST; float* A=d_alpha+(size_t)b*HIST;
    __shared__ float red[256];
    int tid=threadIdx.x;
    float m=-1e30f;
    for(int j=tid;j<HIST;j+=256) m=fmaxf(m,L[j]);
    red[tid]=m; __syncthreads();
    for(int s=128;s>0;s>>=1){ if(tid<s) red[tid]=fmaxf(red[tid],red[tid+s]); __syncthreads(); }
    m=red[0]; __syncthreads();
    float sum=0.f;
    for(int j=tid;j<HIST;j+=256){ float e=expf(L[j]-m); A[j]=e; sum+=e; }
    red[tid]=sum; __syncthreads();
    for(int s=128;s>0;s>>=1){ if(tid<s) red[tid]+=red[tid+s]; __syncthreads(); }
    float inv=1.f/red[0];
    for(int j=tid;j<HIST;j+=256) A[j]*=inv;
}
__global__ __launch_bounds__(256) void sigma_kernel(){
    int b=blockIdx.x, d=threadIdx.x;
    float t=d_sig[(size_t)b*DIN+d];
    d_inv_sigma[(size_t)b*DIN+d]=expf(-t);
    __shared__ float red[256];
    red[d]=t; __syncthreads();
    for(int s=128;s>0;s>>=1){ if(d<s) red[d]+=red[d+s]; __syncthreads(); }
    if(d==0) d_logdet[b]=red[0];
}
__global__ __launch_bounds__(256) void logprob_kernel(
        const float* __restrict__ x, float* __restrict__ out){
    int w=(blockIdx.x<<3)+(threadIdx.x>>5);
    int lane=threadIdx.x&31, b=w&255;
    const float4* xr=(const float4*)(x+((size_t)w<<8));
    const float4* mu=(const float4*)(d_mu+((size_t)b<<8));
    const float4* iv=(const float4*)(d_inv_sigma+((size_t)b<<8));
    float acc=0.f;
#pragma unroll
    for(int c=0;c<2;c++){
        int idx=lane+(c<<5);
        float4 xv=xr[idx], mv=mu[idx], sv=iv[idx];
        float d0=(xv.x-mv.x)*sv.x, d1=(xv.y-mv.y)*sv.y;
        float d2=(xv.z-mv.z)*sv.z, d3=(xv.w-mv.w)*sv.w;
        acc+=d0*d0+d1*d1+d2*d2+d3*d3;
    }
#pragma unroll
    for(int o=16;o;o>>=1) acc+=__shfl_xor_sync(0xffffffffu,acc,o);
    if(lane==0){
        const float log2pi=1.8378770664093453f;
        out[w]=-0.5f*(acc+256.0f*log2pi)-d_logdet[b];
    }
}

// ---------------- launch ----------------
extern "C" void kernel_launch(void* const* d_in, const int* in_sizes, int n_in,
                              void* d_out, int out_size){
    const float* x        = (const float*)d_in[0];
    const float* hidden   = (const float*)d_in[1];
    const float* external = (const float*)d_in[2];
    const float* w_ih     = (const float*)d_in[3];
    const float* w_hh     = (const float*)d_in[4];
    const float* w_alpha  = (const float*)d_in[5];
    const float* w_sigma  = (const float*)d_in[6];
    float* out = (float*)d_out;

    float *pH0, *pG, *pSig, *pAlpha, *pMu;
    cudaGetSymbolAddress((void**)&pH0, d_h);
    cudaGetSymbolAddress((void**)&pG, d_g);
    cudaGetSymbolAddress((void**)&pSig, d_sig);
    cudaGetSymbolAddress((void**)&pAlpha, d_alpha);
    cudaGetSymbolAddress((void**)&pMu, d_mu);

    cudaFuncSetAttribute(gru_hmma, cudaFuncAttributeMaxDynamicSharedMemorySize, SMEM_DYN);

    reset_barrier_kernel<<<1,1>>>();
    pack_x_kernel<<<131072,256>>>(x);
    pack_w_kernel<<<4608,256>>>(w_ih, w_hh);
    pack_h0_kernel<<<512,256>>>(hidden);

    gru_hmma<<<NB,256,SMEM_DYN>>>();        // final h lands in d_h[0]

    gemm_tile_kernel<1><<<8*32,128>>>(pH0, HID, w_alpha, HID, pG, HIST, HID, 32);
    softmax_kernel<<<BATCH,256>>>();
    gemm_tile_kernel<1><<<8*4,128>>>(pH0, HID, w_sigma, HID, pSig, DIN, HID, 4);
    sigma_kernel<<<BATCH,256>>>();
    gemm_tile_kernel<0><<<8*4,128>>>(pAlpha, HIST, external, DIN, pMu, DIN, HIST, 4);
    logprob_kernel<<<(S_LEN*BATCH)/8,256>>>(x, out);
}

// round 15
// speedup vs baseline: 2.2977x; 2.2977x over previous
#include <cuda_runtime.h>
#include <cuda_bf16.h>
#include <math.h>

#define S_LEN 512
#define BATCH 256
#define DIN   256
#define HID   512
#define HIST  2048
#define NB    128
#define SW_BYTES (144*1280)                 /* 184320: 24kc*3p*2term tiles of 16x40 shorts */
#define SA_STAGE 5120                       /* 64 rows x 40 shorts x 2B */
#define SMEM_DYN (SW_BYTES + 4*SA_STAGE)    /* 204800 */

// ---------------- device scratch ----------------
// x image: [t][rt4][kc8][row64][kl32] bf16 (hi only)
__device__ unsigned short d_xbf[(size_t)S_LEN*4*8*2048];     // 64MB
// h image: [par2][rt4][kc16][row64][kl32]
__device__ unsigned short d_hbf[2*4*16*2048];
// W image: [ct32][kc24][p3][term2][j16][kl32]  (hi+lo)
__device__ unsigned short d_wbf[32*24*3*2*512];
__device__ float d_h[2][BATCH*HID];
__device__ float d_g[BATCH*HIST];
__device__ float d_alpha[BATCH*HIST];
__device__ float d_sig[BATCH*DIN];
__device__ float d_mu[BATCH*DIN];
__device__ float d_inv_sigma[BATCH*DIN];
__device__ float d_logdet[BATCH];
__device__ unsigned int g_arrive;
__device__ volatile unsigned int g_release;

__global__ void reset_barrier_kernel() { g_arrive = 0; g_release = 0; }

// ---------------- PTX helpers ----------------
__device__ __forceinline__ unsigned smem_u32(const void* p){
    unsigned a; asm("{ .reg .u64 t; cvta.to.shared.u64 t, %1; cvt.u32.u64 %0, t; }":"=r"(a):"l"(p)); return a;
}
__device__ __forceinline__ void ldsm4(unsigned* r, unsigned addr){
    asm volatile("ldmatrix.sync.aligned.m8n8.x4.shared.b16 {%0,%1,%2,%3}, [%4];"
        : "=r"(r[0]),"=r"(r[1]),"=r"(r[2]),"=r"(r[3]) : "r"(addr));
}
__device__ __forceinline__ void mma16816(float* c, const unsigned* a, unsigned b0, unsigned b1){
    asm volatile("mma.sync.aligned.m16n8k16.row.col.f32.bf16.bf16.f32 "
        "{%0,%1,%2,%3}, {%4,%5,%6,%7}, {%8,%9}, {%0,%1,%2,%3};"
        : "+f"(c[0]),"+f"(c[1]),"+f"(c[2]),"+f"(c[3])
        : "r"(a[0]),"r"(a[1]),"r"(a[2]),"r"(a[3]), "r"(b0),"r"(b1));
}
__device__ __forceinline__ void cpasync16(unsigned s, const void* g){
    asm volatile("cp.async.cg.shared.global [%0], [%1], 16;" :: "r"(s), "l"(g));
}
__device__ __forceinline__ void cpcommit(){ asm volatile("cp.async.commit_group;"); }
__device__ __forceinline__ void cpwait2(){ asm volatile("cp.async.wait_group 2;" ::: "memory"); }
__device__ __forceinline__ void cpwait1(){ asm volatile("cp.async.wait_group 1;" ::: "memory"); }
__device__ __forceinline__ void cpwait0(){ asm volatile("cp.async.wait_group 0;" ::: "memory"); }
__device__ __forceinline__ float sigm(float x){ return 1.f/(1.f+expf(-x)); }

// ---------------- packing ----------------
__global__ __launch_bounds__(256) void pack_x_kernel(const float* __restrict__ x){
    unsigned idx = blockIdx.x*256u + threadIdx.x;
    int kl=idx&31, row=(idx>>5)&63, kc=(idx>>11)&7, rt=(idx>>14)&3, t=idx>>16;
    float v = x[((size_t)t*256 + rt*64 + row)*256 + kc*32 + kl];
    __nv_bfloat16 h = __float2bfloat16(v);
    d_xbf[idx] = *(unsigned short*)&h;
}
__global__ __launch_bounds__(256) void pack_h0_kernel(const float* __restrict__ hidden){
    unsigned idx = blockIdx.x*256u + threadIdx.x;
    int kl=idx&31, row=(idx>>5)&63, kc8=(idx>>11)&15, rt=idx>>15;
    float v = hidden[(size_t)(rt*64+row)*512 + kc8*32 + kl];
    __nv_bfloat16 h = __float2bfloat16(v);
    d_hbf[((size_t)(0*4+rt)*16 + kc8)*2048 + row*32 + kl] = *(unsigned short*)&h;
    d_h[0][(size_t)(rt*64+row)*512 + kc8*32 + kl] = v;
}
__global__ __launch_bounds__(256) void pack_w_kernel(const float* __restrict__ w_ih,
                                                     const float* __restrict__ w_hh){
    unsigned idx = blockIdx.x*256u + threadIdx.x;
    int kl = idx&31, j = (idx>>5)&15;
    int g = idx>>9;
    int p = g%3, kc = (g/3)%24, ct = g/72;
    int kg = kc*32 + kl;
    float w;
    if (p == 0){ int r = ct*16+j;        w = (kg<256)? w_ih[r*256+kg] : w_hh[r*512+kg-256]; }
    else if(p==1){ int r = 512+ct*16+j;  w = (kg<256)? w_ih[r*256+kg] : w_hh[r*512+kg-256]; }
    else { int r = 1024+ct*16+j;
           w = (kc<8)? w_ih[r*256+kg] : w_hh[r*512+kg-256]; }
    __nv_bfloat16 h = __float2bfloat16(w);
    __nv_bfloat16 l = __float2bfloat16(w - __bfloat162float(h));
    size_t base = (size_t)(ct*24+kc)*3072 + (p*2)*512 + j*32 + kl;
    d_wbf[base]       = *(unsigned short*)&h;
    d_wbf[base + 512] = *(unsigned short*)&l;
}

// ---------------- persistent HMMA GRU (8 warps, compile-time reg indexing) ----------------
__device__ __forceinline__ void grid_barrier(unsigned gen){
    __threadfence();
    __syncthreads();
    if(threadIdx.x==0){
        unsigned prev = atomicAdd(&g_arrive, 1u);
        if(prev == NB-1){ g_arrive = 0; __threadfence(); g_release = gen; }
        else { while(g_release < gen) {} __threadfence(); }
    }
    __syncthreads();
}

__device__ __forceinline__ void issue_chunk(int t,int par,int rt,int kc,int stage,
                                            unsigned sAb,int tid){
    const unsigned short* s0 = (kc<8)
        ? d_xbf + ((size_t)(t*4+rt)*8+kc)*2048
        : d_hbf + ((size_t)(par*4+rt)*16+(kc-8))*2048;
    unsigned db = sAb + (unsigned)stage*SA_STAGE;
    int row = tid>>2, q = tid&3;                   // 256 threads -> 4KB
    cpasync16(db + 2u*(unsigned)(row*40 + q*8), s0 + row*32 + q*8);
}

// all register-array indices inside are compile-time constants; nbs branch is warp-uniform
__device__ __forceinline__ void compute_kc(unsigned sWb, unsigned aAddr, int kc, int nbs,
        unsigned laneoff,
        float (&accR)[4], float (&accZ)[4], float (&accN)[4]){
#pragma unroll
    for(int ks=0; ks<2; ks++){
        unsigned ko = (unsigned)(ks*32);
        unsigned ah[4];
        ldsm4(ah, aAddr + ko);
#pragma unroll
        for(int p=0;p<3;p++){
            unsigned bh[4], bl[4];
            unsigned tb = sWb + (unsigned)((kc*6 + p*2)*1280);
            ldsm4(bh, tb + laneoff + ko);
            ldsm4(bl, tb + 1280u + laneoff + ko);
            float* acc = (p==0)? accR : (p==1)? accZ : accN;
            if(nbs==0){
                mma16816(acc, ah, bh[0], bh[2]);
                mma16816(acc, ah, bl[0], bl[2]);
            } else {
                mma16816(acc, ah, bh[1], bh[3]);
                mma16816(acc, ah, bl[1], bl[3]);
            }
        }
    }
}

__global__ __launch_bounds__(256,1) void gru_hmma(){
    extern __shared__ __align__(16) unsigned short sm[];
    const int tid = threadIdx.x, lane = tid&31, w = tid>>5;
    const int rw = w&3, nbs = w>>2;                // row quarter, col half
    const int bid = blockIdx.x, rt = bid>>5, ct = bid&31;
    const unsigned sWb = smem_u32(sm);
    const unsigned sAb = sWb + SW_BYTES;
    const int sub8 = lane>>3;
    const unsigned laneoff = 2u*(unsigned)((((lane&7)+((sub8&1)<<3))*40) + ((sub8>>1)<<3));

    // one-time weight preload (all 24 kc chunks, hi+lo, 3 panels)
    {
        const unsigned short* wsrc = d_wbf + (size_t)ct*24*3072;
        for(int i=tid; i<9216; i+=256){            // 16B units
            int tile = i>>6, r2 = i&63, j = r2>>2, q = r2&3;
            cpasync16(sWb + (unsigned)(tile*1280) + 2u*(unsigned)(j*40+q*8),
                      wsrc + tile*512 + j*32 + q*8);
        }
        cpcommit(); cpwait0(); __syncthreads();
    }

    // prologue: chunks 0..2 of step 0
    issue_chunk(0,0,rt,0,0,sAb,tid); cpcommit();
    issue_chunk(0,0,rt,1,1,sAb,tid); cpcommit();
    issue_chunk(0,0,rt,2,2,sAb,tid); cpcommit();

    const int grow0 = rt*64 + rw*16 + (lane>>2);
    const int gcol  = ct*16 + nbs*8 + 2*(lane&3);
    const int klb   = (ct&1)*16 + nbs*8 + 2*(lane&3);
    const int rowl0 = rw*16 + (lane>>2);

    for(int t=0; t<S_LEN; ++t){
        const int par = t&1;
        float accR[4], accZ[4], accI[4], accH[4];
#pragma unroll
        for(int i=0;i<4;i++){ accR[i]=0.f; accZ[i]=0.f; accI[i]=0.f; accH[i]=0.f; }

        // x chunks 0..7 -> accI (accumulator bound at compile time)
        for(int kc=0; kc<8; ++kc){
            cpwait2();
            __syncthreads();
            issue_chunk(t,par,rt,kc+3,(kc+3)&3,sAb,tid); cpcommit();
            unsigned aAddr = sAb + (unsigned)((kc&3)*SA_STAGE) + (unsigned)(rw*1280) + laneoff;
            compute_kc(sWb, aAddr, kc, nbs, laneoff, accR, accZ, accI);
        }
        // h chunks 8..23 -> accH
        for(int kc=8; kc<24; ++kc){
            if(kc<22) cpwait2(); else if(kc==22) cpwait1(); else cpwait0();
            __syncthreads();
            if(kc<21){ issue_chunk(t,par,rt,kc+3,(kc+3)&3,sAb,tid); cpcommit(); }
            unsigned aAddr = sAb + (unsigned)((kc&3)*SA_STAGE) + (unsigned)(rw*1280) + laneoff;
            compute_kc(sWb, aAddr, kc, nbs, laneoff, accR, accZ, accH);
        }

        // ---- fused gate epilogue (8-warp mapping verified R13/R14) ----
        const float* hprevB = d_h[par];
        float* houtB = d_h[par^1];
        const size_t imgB = (((size_t)(par^1)*4 + rt)*16 + (ct>>1))*2048;
#pragma unroll
        for(int rh=0; rh<2; rh++){
            int f = rh*2;
            int grow = grow0 + rh*8;
            float2 hp = *(const float2*)&hprevB[(size_t)grow*512 + gcol];
            float r0 = sigm(accR[f]),   r1 = sigm(accR[f+1]);
            float z0 = sigm(accZ[f]),   z1 = sigm(accZ[f+1]);
            float n0 = tanhf(accI[f]   + r0*accH[f]);
            float n1 = tanhf(accI[f+1] + r1*accH[f+1]);
            float h0 = (1.f-z0)*n0 + z0*hp.x;
            float h1 = (1.f-z1)*n1 + z1*hp.y;
            *(float2*)&houtB[(size_t)grow*512 + gcol] = make_float2(h0,h1);
            __nv_bfloat16 bh0=__float2bfloat16(h0), bh1=__float2bfloat16(h1);
            *(unsigned*)&d_hbf[imgB + (size_t)(rowl0 + rh*8)*32 + klb] =
                (unsigned)*(unsigned short*)&bh0 | ((unsigned)*(unsigned short*)&bh1 << 16);
        }

        // pre-issue next step's x chunks (0..2) — independent of h
        if(t+1 < S_LEN){
            issue_chunk(t+1,par^1,rt,0,0,sAb,tid); cpcommit();
            issue_chunk(t+1,par^1,rt,1,1,sAb,tid); cpcommit();
            issue_chunk(t+1,par^1,rt,2,2,sAb,tid); cpcommit();
        }
        grid_barrier((unsigned)(t+1));
    }
}

// ---------------- tail: generic tiled GEMM ----------------
template <int TRANSB>
__global__ __launch_bounds__(128) void gemm_tile_kernel(
        const float* __restrict__ A, int lda, const float* __restrict__ Bm, int ldb,
        float* __restrict__ C, int ldc, int K, int colTiles){
    int bid=blockIdx.x, rt=bid/colTiles, ct=bid%colTiles;
    int row0=rt*32, col0=ct*64;
    __shared__ __align__(16) float sA[16][36];
    __shared__ __align__(16) float sB[16][68];
    int tid=threadIdx.x, tr=tid>>4, tc=tid&15;
    float acc[4][4];
#pragma unroll
    for(int i=0;i<4;i++)
#pragma unroll
        for(int j=0;j<4;j++) acc[i][j]=0.f;
    for(int kk0=0;kk0<K;kk0+=16){
#pragma unroll
        for(int it=0;it<4;it++){ int idx=tid+it*128; int k=idx&15, r=idx>>4;
            sA[k][r]=A[(size_t)(row0+r)*lda+kk0+k]; }
        if(TRANSB){
#pragma unroll
            for(int it=0;it<8;it++){ int idx=tid+it*128; int k=idx&15, j=idx>>4;
                sB[k][j]=Bm[(size_t)(col0+j)*ldb+kk0+k]; }
        } else {
#pragma unroll
            for(int it=0;it<8;it++){ int idx=tid+it*128; int j=idx&63, k=idx>>6;
                sB[k][j]=Bm[(size_t)(kk0+k)*ldb+col0+j]; }
        }
        __syncthreads();
#pragma unroll
        for(int k=0;k<16;k++){
            float4 av=*(const float4*)&sA[k][tr<<2];
            float4 bv=*(const float4*)&sB[k][tc<<2];
            float a[4]={av.x,av.y,av.z,av.w}, b[4]={bv.x,bv.y,bv.z,bv.w};
#pragma unroll
            for(int i=0;i<4;i++)
#pragma unroll
                for(int j=0;j<4;j++) acc[i][j]+=a[i]*b[j];
        }
        __syncthreads();
    }
#pragma unroll
    for(int i=0;i<4;i++){
        float4 v=make_float4(acc[i][0],acc[i][1],acc[i][2],acc[i][3]);
        *(float4*)&C[(size_t)(row0+(tr<<2)+i)*ldc+col0+(tc<<2)]=v;
    }
}

__global__ __launch_bounds__(256) void softmax_kernel(){
    int b=blockIdx.x;
    const float* L=d_g+(size_t)b*HIST; float* A=d_alpha+(size_t)b*HIST;
    __shared__ float red[256];
    int tid=threadIdx.x;
    float m=-1e30f;
    for(int j=tid;j<HIST;j+=256) m=fmaxf(m,L[j]);
    red[tid]=m; __syncthreads();
    for(int s=128;s>0;s>>=1){ if(tid<s) red[tid]=fmaxf(red[tid],red[tid+s]); __syncthreads(); }
    m=red[0]; __syncthreads();
    float sum=0.f;
    for(int j=tid;j<HIST;j+=256){ float e=expf(L[j]-m); A[j]=e; sum+=e; }
    red[tid]=sum; __syncthreads();
    for(int s=128;s>0;s>>=1){ if(tid<s) red[tid]+=red[tid+s]; __syncthreads(); }
    float inv=1.f/red[0];
    for(int j=tid;j<HIST;j+=256) A[j]*=inv;
}
__global__ __launch_bounds__(256) void sigma_kernel(){
    int b=blockIdx.x, d=threadIdx.x;
    float t=d_sig[(size_t)b*DIN+d];
    d_inv_sigma[(size_t)b*DIN+d]=expf(-t);
    __shared__ float red[256];
    red[d]=t; __syncthreads();
    for(int s=128;s>0;s>>=1){ if(d<s) red[d]+=red[d+s]; __syncthreads(); }
    if(d==0) d_logdet[b]=red[0];
}
__global__ __launch_bounds__(256) void logprob_kernel(
        const float* __restrict__ x, float* __restrict__ out){
    int w=(blockIdx.x<<3)+(threadIdx.x>>5);
    int lane=threadIdx.x&31, b=w&255;
    const float4* xr=(const float4*)(x+((size_t)w<<8));
    const float4* mu=(const float4*)(d_mu+((size_t)b<<8));
    const float4* iv=(const float4*)(d_inv_sigma+((size_t)b<<8));
    float acc=0.f;
#pragma unroll
    for(int c=0;c<2;c++){
        int idx=lane+(c<<5);
        float4 xv=xr[idx], mv=mu[idx], sv=iv[idx];
        float d0=(xv.x-mv.x)*sv.x, d1=(xv.y-mv.y)*sv.y;
        float d2=(xv.z-mv.z)*sv.z, d3=(xv.w-mv.w)*sv.w;
        acc+=d0*d0+d1*d1+d2*d2+d3*d3;
    }
#pragma unroll
    for(int o=16;o;o>>=1) acc+=__shfl_xor_sync(0xffffffffu,acc,o);
    if(lane==0){
        const float log2pi=1.8378770664093453f;
        out[w]=-0.5f*(acc+256.0f*log2pi)-d_logdet[b];
    }
}

// ---------------- launch ----------------
extern "C" void kernel_launch(void* const* d_in, const int* in_sizes, int n_in,
                              void* d_out, int out_size){
    const float* x        = (const float*)d_in[0];
    const float* hidden   = (const float*)d_in[1];
    const float* external = (const float*)d_in[2];
    const float* w_ih     = (const float*)d_in[3];
    const float* w_hh     = (const float*)d_in[4];
    const float* w_alpha  = (const float*)d_in[5];
    const float* w_sigma  = (const float*)d_in[6];
    float* out = (float*)d_out;

    float *pH0, *pG, *pSig, *pAlpha, *pMu;
    cudaGetSymbolAddress((void**)&pH0, d_h);
    cudaGetSymbolAddress((void**)&pG, d_g);
    cudaGetSymbolAddress((void**)&pSig, d_sig);
    cudaGetSymbolAddress((void**)&pAlpha, d_alpha);
    cudaGetSymbolAddress((void**)&pMu, d_mu);

    cudaFuncSetAttribute(gru_hmma, cudaFuncAttributeMaxDynamicSharedMemorySize, SMEM_DYN);

    reset_barrier_kernel<<<1,1>>>();
    pack_x_kernel<<<131072,256>>>(x);
    pack_w_kernel<<<4608,256>>>(w_ih, w_hh);
    pack_h0_kernel<<<512,256>>>(hidden);

    gru_hmma<<<NB,256,SMEM_DYN>>>();        // final h lands in d_h[0]

    gemm_tile_kernel<1><<<8*32,128>>>(pH0, HID, w_alpha, HID, pG, HIST, HID, 32);
    softmax_kernel<<<BATCH,256>>>();
    gemm_tile_kernel<1><<<8*4,128>>>(pH0, HID, w_sigma, HID, pSig, DIN, HID, 4);
    sigma_kernel<<<BATCH,256>>>();
    gemm_tile_kernel<0><<<8*4,128>>>(pAlpha, HIST, external, DIN, pMu, DIN, HIST, 4);
    logprob_kernel<<<(S_LEN*BATCH)/8,256>>>(x, out);
}

// round 16
// speedup vs baseline: 3.4065x; 1.4825x over previous
#include <cuda_runtime.h>
#include <cuda_bf16.h>
#include <math.h>

#define S_LEN 512
#define BATCH 256
#define DIN   256
#define HID   512
#define HIST  2048
#define NB    128
#define SW_BYTES (144*1280)                 /* 184320: 24kc*3p*2term tiles of 16x40 shorts */
#define SA_STAGE 5120                       /* 64 rows x 40 shorts x 2B */
#define SMEM_DYN (SW_BYTES + 4*SA_STAGE)    /* 204800 */

// ---------------- device scratch ----------------
// x image: [t][rt4][kc8][row64][kl32] bf16 (hi only)
__device__ unsigned short d_xbf[(size_t)S_LEN*4*8*2048];     // 64MB
// h image: [par2][rt4][kc16][row64][kl32]
__device__ unsigned short d_hbf[2*4*16*2048];
// W image: [ct32][kc24][p3][term2][j16][kl32]  (hi+lo)
__device__ unsigned short d_wbf[32*24*3*2*512];
__device__ float d_h[2][BATCH*HID];
__device__ float d_g[BATCH*HIST];
__device__ float d_alpha[BATCH*HIST];
__device__ float d_sig[BATCH*DIN];
__device__ float d_mu[BATCH*DIN];
__device__ float d_inv_sigma[BATCH*DIN];
__device__ float d_logdet[BATCH];
__device__ unsigned int g_arrive;
__device__ volatile unsigned int g_release;

__global__ void reset_barrier_kernel() { g_arrive = 0; g_release = 0; }

// ---------------- PTX helpers ----------------
__device__ __forceinline__ unsigned smem_u32(const void* p){
    unsigned a; asm("{ .reg .u64 t; cvta.to.shared.u64 t, %1; cvt.u32.u64 %0, t; }":"=r"(a):"l"(p)); return a;
}
__device__ __forceinline__ void ldsm4(unsigned* r, unsigned addr){
    asm volatile("ldmatrix.sync.aligned.m8n8.x4.shared.b16 {%0,%1,%2,%3}, [%4];"
        : "=r"(r[0]),"=r"(r[1]),"=r"(r[2]),"=r"(r[3]) : "r"(addr));
}
__device__ __forceinline__ void mma16816(float* c, const unsigned* a, unsigned b0, unsigned b1){
    asm volatile("mma.sync.aligned.m16n8k16.row.col.f32.bf16.bf16.f32 "
        "{%0,%1,%2,%3}, {%4,%5,%6,%7}, {%8,%9}, {%0,%1,%2,%3};"
        : "+f"(c[0]),"+f"(c[1]),"+f"(c[2]),"+f"(c[3])
        : "r"(a[0]),"r"(a[1]),"r"(a[2]),"r"(a[3]), "r"(b0),"r"(b1));
}
__device__ __forceinline__ void cpasync16(unsigned s, const void* g){
    asm volatile("cp.async.cg.shared.global [%0], [%1], 16;" :: "r"(s), "l"(g));
}
__device__ __forceinline__ void cpcommit(){ asm volatile("cp.async.commit_group;"); }
__device__ __forceinline__ void cpwait2(){ asm volatile("cp.async.wait_group 2;" ::: "memory"); }
__device__ __forceinline__ void cpwait1(){ asm volatile("cp.async.wait_group 1;" ::: "memory"); }
__device__ __forceinline__ void cpwait0(){ asm volatile("cp.async.wait_group 0;" ::: "memory"); }
__device__ __forceinline__ float sigm(float x){ return 1.f/(1.f+expf(-x)); }

// ---------------- packing ----------------
__global__ __launch_bounds__(256) void pack_x_kernel(const float* __restrict__ x){
    unsigned idx = blockIdx.x*256u + threadIdx.x;
    int kl=idx&31, row=(idx>>5)&63, kc=(idx>>11)&7, rt=(idx>>14)&3, t=idx>>16;
    float v = x[((size_t)t*256 + rt*64 + row)*256 + kc*32 + kl];
    __nv_bfloat16 h = __float2bfloat16(v);
    d_xbf[idx] = *(unsigned short*)&h;
}
__global__ __launch_bounds__(256) void pack_h0_kernel(const float* __restrict__ hidden){
    unsigned idx = blockIdx.x*256u + threadIdx.x;
    int kl=idx&31, row=(idx>>5)&63, kc8=(idx>>11)&15, rt=idx>>15;
    float v = hidden[(size_t)(rt*64+row)*512 + kc8*32 + kl];
    __nv_bfloat16 h = __float2bfloat16(v);
    d_hbf[((size_t)(0*4+rt)*16 + kc8)*2048 + row*32 + kl] = *(unsigned short*)&h;
    d_h[0][(size_t)(rt*64+row)*512 + kc8*32 + kl] = v;
}
__global__ __launch_bounds__(256) void pack_w_kernel(const float* __restrict__ w_ih,
                                                     const float* __restrict__ w_hh){
    unsigned idx = blockIdx.x*256u + threadIdx.x;
    int kl = idx&31, j = (idx>>5)&15;
    int g = idx>>9;
    int p = g%3, kc = (g/3)%24, ct = g/72;
    int kg = kc*32 + kl;
    float w;
    if (p == 0){ int r = ct*16+j;        w = (kg<256)? w_ih[r*256+kg] : w_hh[r*512+kg-256]; }
    else if(p==1){ int r = 512+ct*16+j;  w = (kg<256)? w_ih[r*256+kg] : w_hh[r*512+kg-256]; }
    else { int r = 1024+ct*16+j;
           w = (kc<8)? w_ih[r*256+kg] : w_hh[r*512+kg-256]; }
    __nv_bfloat16 h = __float2bfloat16(w);
    __nv_bfloat16 l = __float2bfloat16(w - __bfloat162float(h));
    size_t base = (size_t)(ct*24+kc)*3072 + (p*2)*512 + j*32 + kl;
    d_wbf[base]       = *(unsigned short*)&h;
    d_wbf[base + 512] = *(unsigned short*)&l;
}

// ---------------- persistent HMMA GRU (4 warps, barrier-free inner loop) ----------------
__device__ __forceinline__ void grid_barrier(unsigned gen){
    __threadfence();
    __syncthreads();
    if(threadIdx.x==0){
        unsigned prev = atomicAdd(&g_arrive, 1u);
        if(prev == NB-1){ g_arrive = 0; __threadfence(); g_release = gen; }
        else { while(g_release < gen) {} __threadfence(); }
    }
    __syncthreads();
}

// per-warp A staging: warp w copies ONLY its own 16 rows (1KB)
__device__ __forceinline__ void issue_chunk_w(int t,int par,int rt,int kc,int stage,
                                              unsigned sAb,int w,int lane){
    const unsigned short* s0 = (kc<8)
        ? d_xbf + ((size_t)(t*4+rt)*8+kc)*2048
        : d_hbf + ((size_t)(par*4+rt)*16+(kc-8))*2048;
    unsigned db = sAb + (unsigned)stage*SA_STAGE;
#pragma unroll
    for(int i=0;i<2;i++){
        int id = lane + (i<<5);                 // 0..63
        int rowL = id>>2, q = id&3;             // 16 rows x 4 quads
        int row = w*16 + rowL;
        cpasync16(db + 2u*(unsigned)(row*40 + q*8), s0 + row*32 + q*8);
    }
}

// full N=16 per warp (R12 shape); all register indices compile-time
__device__ __forceinline__ void compute_kc(unsigned sWb, unsigned aAddr, int kc,
        unsigned laneoff,
        float (&accR)[8], float (&accZ)[8], float (&accN)[8]){
#pragma unroll
    for(int ks=0; ks<2; ks++){
        unsigned ko = (unsigned)(ks*32);
        unsigned ah[4];
        ldsm4(ah, aAddr + ko);
#pragma unroll
        for(int p=0;p<3;p++){
            unsigned bh[4], bl[4];
            unsigned tb = sWb + (unsigned)((kc*6 + p*2)*1280);
            ldsm4(bh, tb + laneoff + ko);
            ldsm4(bl, tb + 1280u + laneoff + ko);
            float* acc = (p==0)? accR : (p==1)? accZ : accN;   // p compile-time
            mma16816(acc,   ah, bh[0], bh[2]);
            mma16816(acc,   ah, bl[0], bl[2]);
            mma16816(acc+4, ah, bh[1], bh[3]);
            mma16816(acc+4, ah, bl[1], bl[3]);
        }
    }
}

__global__ __launch_bounds__(128,1) void gru_hmma(){
    extern __shared__ __align__(16) unsigned short sm[];
    const int tid = threadIdx.x, lane = tid&31, w = tid>>5;   // 4 warps
    const int bid = blockIdx.x, rt = bid>>5, ct = bid&31;
    const unsigned sWb = smem_u32(sm);
    const unsigned sAb = sWb + SW_BYTES;
    const int sub8 = lane>>3;
    const unsigned laneoff = 2u*(unsigned)((((lane&7)+((sub8&1)<<3))*40) + ((sub8>>1)<<3));

    // one-time weight preload (B is immutable afterwards -> no barriers needed on B)
    {
        const unsigned short* wsrc = d_wbf + (size_t)ct*24*3072;
        for(int i=tid; i<9216; i+=128){
            int tile = i>>6, r2 = i&63, j = r2>>2, q = r2&3;
            cpasync16(sWb + (unsigned)(tile*1280) + 2u*(unsigned)(j*40+q*8),
                      wsrc + tile*512 + j*32 + q*8);
        }
        cpcommit(); cpwait0(); __syncthreads();
    }

    // prologue: chunks 0..2 of step 0 (per-warp)
    issue_chunk_w(0,0,rt,0,0,sAb,w,lane); cpcommit();
    issue_chunk_w(0,0,rt,1,1,sAb,w,lane); cpcommit();
    issue_chunk_w(0,0,rt,2,2,sAb,w,lane); cpcommit();

    const int grow0 = rt*64 + w*16 + (lane>>2);
    const int cb = ct*16 + 2*(lane&3);
    const int klb = (ct&1)*16 + 2*(lane&3);
    const int rowl0 = w*16 + (lane>>2);

    for(int t=0; t<S_LEN; ++t){
        const int par = t&1;
        float accR[8], accZ[8], accI[8], accH[8];
#pragma unroll
        for(int i=0;i<8;i++){ accR[i]=0.f; accZ[i]=0.f; accI[i]=0.f; accH[i]=0.f; }

        // x chunks 0..7 -> accI ; barrier-free: per-warp wait + syncwarp only
        for(int kc=0; kc<8; ++kc){
            cpwait2(); __syncwarp();
            issue_chunk_w(t,par,rt,kc+3,(kc+3)&3,sAb,w,lane); cpcommit();
            unsigned aAddr = sAb + (unsigned)((kc&3)*SA_STAGE) + (unsigned)(w*1280) + laneoff;
            compute_kc(sWb, aAddr, kc, laneoff, accR, accZ, accI);
        }
        // h chunks 8..23 -> accH
        for(int kc=8; kc<24; ++kc){
            if(kc<22){ cpwait2(); } else if(kc==22){ cpwait1(); } else { cpwait0(); }
            __syncwarp();
            if(kc<21){ issue_chunk_w(t,par,rt,kc+3,(kc+3)&3,sAb,w,lane); cpcommit(); }
            unsigned aAddr = sAb + (unsigned)((kc&3)*SA_STAGE) + (unsigned)(w*1280) + laneoff;
            compute_kc(sWb, aAddr, kc, laneoff, accR, accZ, accH);
        }

        // ---- fused gate epilogue (R12-verified mapping) ----
        const float* hprevB = d_h[par];
        float* houtB = d_h[par^1];
        const size_t imgB = (((size_t)(par^1)*4 + rt)*16 + (ct>>1))*2048;
#pragma unroll
        for(int nb=0; nb<2; nb++)
#pragma unroll
        for(int rh=0; rh<2; rh++){
            int f = nb*4 + rh*2;
            int grow = grow0 + rh*8;
            int gcol = cb + nb*8;
            float2 hp = *(const float2*)&hprevB[(size_t)grow*512 + gcol];
            float r0 = sigm(accR[f]),   r1 = sigm(accR[f+1]);
            float z0 = sigm(accZ[f]),   z1 = sigm(accZ[f+1]);
            float n0 = tanhf(accI[f]   + r0*accH[f]);
            float n1 = tanhf(accI[f+1] + r1*accH[f+1]);
            float h0 = (1.f-z0)*n0 + z0*hp.x;
            float h1 = (1.f-z1)*n1 + z1*hp.y;
            *(float2*)&houtB[(size_t)grow*512 + gcol] = make_float2(h0,h1);
            __nv_bfloat16 bh0=__float2bfloat16(h0), bh1=__float2bfloat16(h1);
            *(unsigned*)&d_hbf[imgB + (size_t)(rowl0 + rh*8)*32 + klb + nb*8] =
                (unsigned)*(unsigned short*)&bh0 | ((unsigned)*(unsigned short*)&bh1 << 16);
        }

        // pre-issue next step's x chunks (0..2) — independent of h
        if(t+1 < S_LEN){
            issue_chunk_w(t+1,par^1,rt,0,0,sAb,w,lane); cpcommit();
            issue_chunk_w(t+1,par^1,rt,1,1,sAb,w,lane); cpcommit();
            issue_chunk_w(t+1,par^1,rt,2,2,sAb,w,lane); cpcommit();
        }
        grid_barrier((unsigned)(t+1));
    }
}

// ---------------- tail: generic tiled GEMM ----------------
template <int TRANSB>
__global__ __launch_bounds__(128) void gemm_tile_kernel(
        const float* __restrict__ A, int lda, const float* __restrict__ Bm, int ldb,
        float* __restrict__ C, int ldc, int K, int colTiles){
    int bid=blockIdx.x, rt=bid/colTiles, ct=bid%colTiles;
    int row0=rt*32, col0=ct*64;
    __shared__ __align__(16) float sA[16][36];
    __shared__ __align__(16) float sB[16][68];
    int tid=threadIdx.x, tr=tid>>4, tc=tid&15;
    float acc[4][4];
#pragma unroll
    for(int i=0;i<4;i++)
#pragma unroll
        for(int j=0;j<4;j++) acc[i][j]=0.f;
    for(int kk0=0;kk0<K;kk0+=16){
#pragma unroll
        for(int it=0;it<4;it++){ int idx=tid+it*128; int k=idx&15, r=idx>>4;
            sA[k][r]=A[(size_t)(row0+r)*lda+kk0+k]; }
        if(TRANSB){
#pragma unroll
            for(int it=0;it<8;it++){ int idx=tid+it*128; int k=idx&15, j=idx>>4;
                sB[k][j]=Bm[(size_t)(col0+j)*ldb+kk0+k]; }
        } else {
#pragma unroll
            for(int it=0;it<8;it++){ int idx=tid+it*128; int j=idx&63, k=idx>>6;
                sB[k][j]=Bm[(size_t)(kk0+k)*ldb+col0+j]; }
        }
        __syncthreads();
#pragma unroll
        for(int k=0;k<16;k++){
            float4 av=*(const float4*)&sA[k][tr<<2];
            float4 bv=*(const float4*)&sB[k][tc<<2];
            float a[4]={av.x,av.y,av.z,av.w}, b[4]={bv.x,bv.y,bv.z,bv.w};
#pragma unroll
            for(int i=0;i<4;i++)
#pragma unroll
                for(int j=0;j<4;j++) acc[i][j]+=a[i]*b[j];
        }
        __syncthreads();
    }
#pragma unroll
    for(int i=0;i<4;i++){
        float4 v=make_float4(acc[i][0],acc[i][1],acc[i][2],acc[i][3]);
        *(float4*)&C[(size_t)(row0+(tr<<2)+i)*ldc+col0+(tc<<2)]=v;
    }
}

__global__ __launch_bounds__(256) void softmax_kernel(){
    int b=blockIdx.x;
    const float* L=d_g+(size_t)b*HIST; float* A=d_alpha+(size_t)b*HIST;
    __shared__ float red[256];
    int tid=threadIdx.x;
    float m=-1e30f;
    for(int j=tid;j<HIST;j+=256) m=fmaxf(m,L[j]);
    red[tid]=m; __syncthreads();
    for(int s=128;s>0;s>>=1){ if(tid<s) red[tid]=fmaxf(red[tid],red[tid+s]); __syncthreads(); }
    m=red[0]; __syncthreads();
    float sum=0.f;
    for(int j=tid;j<HIST;j+=256){ float e=expf(L[j]-m); A[j]=e; sum+=e; }
    red[tid]=sum; __syncthreads();
    for(int s=128;s>0;s>>=1){ if(tid<s) red[tid]+=red[tid+s]; __syncthreads(); }
    float inv=1.f/red[0];
    for(int j=tid;j<HIST;j+=256) A[j]*=inv;
}
__global__ __launch_bounds__(256) void sigma_kernel(){
    int b=blockIdx.x, d=threadIdx.x;
    float t=d_sig[(size_t)b*DIN+d];
    d_inv_sigma[(size_t)b*DIN+d]=expf(-t);
    __shared__ float red[256];
    red[d]=t; __syncthreads();
    for(int s=128;s>0;s>>=1){ if(d<s) red[d]+=red[d+s]; __syncthreads(); }
    if(d==0) d_logdet[b]=red[0];
}
__global__ __launch_bounds__(256) void logprob_kernel(
        const float* __restrict__ x, float* __restrict__ out){
    int w=(blockIdx.x<<3)+(threadIdx.x>>5);
    int lane=threadIdx.x&31, b=w&255;
    const float4* xr=(const float4*)(x+((size_t)w<<8));
    const float4* mu=(const float4*)(d_mu+((size_t)b<<8));
    const float4* iv=(const float4*)(d_inv_sigma+((size_t)b<<8));
    float acc=0.f;
#pragma unroll
    for(int c=0;c<2;c++){
        int idx=lane+(c<<5);
        float4 xv=xr[idx], mv=mu[idx], sv=iv[idx];
        float d0=(xv.x-mv.x)*sv.x, d1=(xv.y-mv.y)*sv.y;
        float d2=(xv.z-mv.z)*sv.z, d3=(xv.w-mv.w)*sv.w;
        acc+=d0*d0+d1*d1+d2*d2+d3*d3;
    }
#pragma unroll
    for(int o=16;o;o>>=1) acc+=__shfl_xor_sync(0xffffffffu,acc,o);
    if(lane==0){
        const float log2pi=1.8378770664093453f;
        out[w]=-0.5f*(acc+256.0f*log2pi)-d_logdet[b];
    }
}

// ---------------- launch ----------------
extern "C" void kernel_launch(void* const* d_in, const int* in_sizes, int n_in,
                              void* d_out, int out_size){
    const float* x        = (const float*)d_in[0];
    const float* hidden   = (const float*)d_in[1];
    const float* external = (const float*)d_in[2];
    const float* w_ih     = (const float*)d_in[3];
    const float* w_hh     = (const float*)d_in[4];
    const float* w_alpha  = (const float*)d_in[5];
    const float* w_sigma  = (const float*)d_in[6];
    float* out = (float*)d_out;

    float *pH0, *pG, *pSig, *pAlpha, *pMu;
    cudaGetSymbolAddress((void**)&pH0, d_h);
    cudaGetSymbolAddress((void**)&pG, d_g);
    cudaGetSymbolAddress((void**)&pSig, d_sig);
    cudaGetSymbolAddress((void**)&pAlpha, d_alpha);
    cudaGetSymbolAddress((void**)&pMu, d_mu);

    cudaFuncSetAttribute(gru_hmma, cudaFuncAttributeMaxDynamicSharedMemorySize, SMEM_DYN);

    reset_barrier_kernel<<<1,1>>>();
    pack_x_kernel<<<131072,256>>>(x);
    pack_w_kernel<<<4608,256>>>(w_ih, w_hh);
    pack_h0_kernel<<<512,256>>>(hidden);

    gru_hmma<<<NB,128,SMEM_DYN>>>();        // final h lands in d_h[0]

    gemm_tile_kernel<1><<<8*32,128>>>(pH0, HID, w_alpha, HID, pG, HIST, HID, 32);
    softmax_kernel<<<BATCH,256>>>();
    gemm_tile_kernel<1><<<8*4,128>>>(pH0, HID, w_sigma, HID, pSig, DIN, HID, 4);
    sigma_kernel<<<BATCH,256>>>();
    gemm_tile_kernel<0><<<8*4,128>>>(pAlpha, HIST, external, DIN, pMu, DIN, HIST, 4);
    logprob_kernel<<<(S_LEN*BATCH)/8,256>>>(x, out);
}

// round 17
// speedup vs baseline: 3.4355x; 1.0085x over previous
#include <cuda_runtime.h>
#include <cuda_bf16.h>
#include <math.h>

#define S_LEN 512
#define BATCH 256
#define DIN   256
#define HID   512
#define HIST  2048
#define NB    128
#define SW_BYTES (144*1280)                 /* 184320: 24kc*3p*2term tiles of 16x40 shorts */
#define SA_STAGE 5120                       /* 64 rows x 40 shorts x 2B */
#define SMEM_DYN (SW_BYTES + 4*SA_STAGE)    /* 204800 */

// ---------------- device scratch ----------------
// x image: [t][rt4][kc8][row64][kl32] bf16 (hi only)
__device__ unsigned short d_xbf[(size_t)S_LEN*4*8*2048];     // 64MB
// h image: [par2][rt4][kc16][row64][kl32]
__device__ unsigned short d_hbf[2*4*16*2048];
// W image: [ct32][kc24][p3][term2][j16][kl32]  (hi+lo)
__device__ unsigned short d_wbf[32*24*3*2*512];
__device__ float d_h[2][BATCH*HID];
__device__ float d_g[BATCH*HIST];
__device__ float d_alpha[BATCH*HIST];
__device__ float d_sig[BATCH*DIN];
__device__ float d_mu[BATCH*DIN];
__device__ float d_inv_sigma[BATCH*DIN];
__device__ float d_logdet[BATCH];
__device__ unsigned int g_arrive;
__device__ volatile unsigned int g_release;

__global__ void reset_barrier_kernel() { g_arrive = 0; g_release = 0; }

// ---------------- PTX helpers ----------------
__device__ __forceinline__ unsigned smem_u32(const void* p){
    unsigned a; asm("{ .reg .u64 t; cvta.to.shared.u64 t, %1; cvt.u32.u64 %0, t; }":"=r"(a):"l"(p)); return a;
}
__device__ __forceinline__ void ldsm4(unsigned* r, unsigned addr){
    asm volatile("ldmatrix.sync.aligned.m8n8.x4.shared.b16 {%0,%1,%2,%3}, [%4];"
        : "=r"(r[0]),"=r"(r[1]),"=r"(r[2]),"=r"(r[3]) : "r"(addr));
}
__device__ __forceinline__ void mma16816(float* c, const unsigned* a, unsigned b0, unsigned b1){
    asm volatile("mma.sync.aligned.m16n8k16.row.col.f32.bf16.bf16.f32 "
        "{%0,%1,%2,%3}, {%4,%5,%6,%7}, {%8,%9}, {%0,%1,%2,%3};"
        : "+f"(c[0]),"+f"(c[1]),"+f"(c[2]),"+f"(c[3])
        : "r"(a[0]),"r"(a[1]),"r"(a[2]),"r"(a[3]), "r"(b0),"r"(b1));
}
__device__ __forceinline__ void cpasync16(unsigned s, const void* g){
    asm volatile("cp.async.cg.shared.global [%0], [%1], 16;" :: "r"(s), "l"(g));
}
__device__ __forceinline__ void cpcommit(){ asm volatile("cp.async.commit_group;"); }
__device__ __forceinline__ void cpwait2(){ asm volatile("cp.async.wait_group 2;" ::: "memory"); }
__device__ __forceinline__ void cpwait1(){ asm volatile("cp.async.wait_group 1;" ::: "memory"); }
__device__ __forceinline__ void cpwait0(){ asm volatile("cp.async.wait_group 0;" ::: "memory"); }
__device__ __forceinline__ float sigm(float x){ return 1.f/(1.f+expf(-x)); }

// ---------------- packing ----------------
__global__ __launch_bounds__(256) void pack_x_kernel(const float* __restrict__ x){
    unsigned idx = blockIdx.x*256u + threadIdx.x;
    int kl=idx&31, row=(idx>>5)&63, kc=(idx>>11)&7, rt=(idx>>14)&3, t=idx>>16;
    float v = x[((size_t)t*256 + rt*64 + row)*256 + kc*32 + kl];
    __nv_bfloat16 h = __float2bfloat16(v);
    d_xbf[idx] = *(unsigned short*)&h;
}
__global__ __launch_bounds__(256) void pack_h0_kernel(const float* __restrict__ hidden){
    unsigned idx = blockIdx.x*256u + threadIdx.x;
    int kl=idx&31, row=(idx>>5)&63, kc8=(idx>>11)&15, rt=idx>>15;
    float v = hidden[(size_t)(rt*64+row)*512 + kc8*32 + kl];
    __nv_bfloat16 h = __float2bfloat16(v);
    d_hbf[((size_t)(0*4+rt)*16 + kc8)*2048 + row*32 + kl] = *(unsigned short*)&h;
    d_h[0][(size_t)(rt*64+row)*512 + kc8*32 + kl] = v;
}
__global__ __launch_bounds__(256) void pack_w_kernel(const float* __restrict__ w_ih,
                                                     const float* __restrict__ w_hh){
    unsigned idx = blockIdx.x*256u + threadIdx.x;
    int kl = idx&31, j = (idx>>5)&15;
    int g = idx>>9;
    int p = g%3, kc = (g/3)%24, ct = g/72;
    int kg = kc*32 + kl;
    float w;
    if (p == 0){ int r = ct*16+j;        w = (kg<256)? w_ih[r*256+kg] : w_hh[r*512+kg-256]; }
    else if(p==1){ int r = 512+ct*16+j;  w = (kg<256)? w_ih[r*256+kg] : w_hh[r*512+kg-256]; }
    else { int r = 1024+ct*16+j;
           w = (kc<8)? w_ih[r*256+kg] : w_hh[r*512+kg-256]; }
    __nv_bfloat16 h = __float2bfloat16(w);
    __nv_bfloat16 l = __float2bfloat16(w - __bfloat162float(h));
    size_t base = (size_t)(ct*24+kc)*3072 + (p*2)*512 + j*32 + kl;
    d_wbf[base]       = *(unsigned short*)&h;
    d_wbf[base + 512] = *(unsigned short*)&l;
}

// ---------------- persistent HMMA GRU (4 warps, split hi/lo accumulators) ----------------
__device__ __forceinline__ void grid_barrier(unsigned gen){
    __threadfence();
    __syncthreads();
    if(threadIdx.x==0){
        unsigned prev = atomicAdd(&g_arrive, 1u);
        if(prev == NB-1){ g_arrive = 0; __threadfence(); g_release = gen; }
        else { while(g_release < gen) {} __threadfence(); }
    }
    __syncthreads();
}

// per-warp A staging: warp w copies ONLY its own 16 rows (1KB)
__device__ __forceinline__ void issue_chunk_w(int t,int par,int rt,int kc,int stage,
                                              unsigned sAb,int w,int lane){
    const unsigned short* s0 = (kc<8)
        ? d_xbf + ((size_t)(t*4+rt)*8+kc)*2048
        : d_hbf + ((size_t)(par*4+rt)*16+(kc-8))*2048;
    unsigned db = sAb + (unsigned)stage*SA_STAGE;
#pragma unroll
    for(int i=0;i<2;i++){
        int id = lane + (i<<5);                 // 0..63
        int rowL = id>>2, q = id&3;             // 16 rows x 4 quads
        int row = w*16 + rowL;
        cpasync16(db + 2u*(unsigned)(row*40 + q*8), s0 + row*32 + q*8);
    }
}

// hi-term and lo-term go to SEPARATE accumulator sets -> no back-to-back RAW on mma
__device__ __forceinline__ void compute_kc(unsigned sWb, unsigned aAddr, int kc,
        unsigned laneoff,
        float (&accR0)[8], float (&accR1)[8],
        float (&accZ0)[8], float (&accZ1)[8],
        float (&accN0)[8], float (&accN1)[8]){
#pragma unroll
    for(int ks=0; ks<2; ks++){
        unsigned ko = (unsigned)(ks*32);
        unsigned ah[4];
        ldsm4(ah, aAddr + ko);
#pragma unroll
        for(int p=0;p<3;p++){
            unsigned bh[4], bl[4];
            unsigned tb = sWb + (unsigned)((kc*6 + p*2)*1280);
            ldsm4(bh, tb + laneoff + ko);
            ldsm4(bl, tb + 1280u + laneoff + ko);
            float* a0 = (p==0)? accR0 : (p==1)? accZ0 : accN0;   // p compile-time
            float* a1 = (p==0)? accR1 : (p==1)? accZ1 : accN1;
            mma16816(a0,   ah, bh[0], bh[2]);
            mma16816(a1,   ah, bl[0], bl[2]);
            mma16816(a0+4, ah, bh[1], bh[3]);
            mma16816(a1+4, ah, bl[1], bl[3]);
        }
    }
}

__global__ __launch_bounds__(128,1) void gru_hmma(){
    extern __shared__ __align__(16) unsigned short sm[];
    const int tid = threadIdx.x, lane = tid&31, w = tid>>5;   // 4 warps
    const int bid = blockIdx.x, rt = bid>>5, ct = bid&31;
    const unsigned sWb = smem_u32(sm);
    const unsigned sAb = sWb + SW_BYTES;
    const int sub8 = lane>>3;
    const unsigned laneoff = 2u*(unsigned)((((lane&7)+((sub8&1)<<3))*40) + ((sub8>>1)<<3));

    // one-time weight preload (B is immutable afterwards)
    {
        const unsigned short* wsrc = d_wbf + (size_t)ct*24*3072;
        for(int i=tid; i<9216; i+=128){
            int tile = i>>6, r2 = i&63, j = r2>>2, q = r2&3;
            cpasync16(sWb + (unsigned)(tile*1280) + 2u*(unsigned)(j*40+q*8),
                      wsrc + tile*512 + j*32 + q*8);
        }
        cpcommit(); cpwait0(); __syncthreads();
    }

    // prologue: chunks 0..2 of step 0 (per-warp)
    issue_chunk_w(0,0,rt,0,0,sAb,w,lane); cpcommit();
    issue_chunk_w(0,0,rt,1,1,sAb,w,lane); cpcommit();
    issue_chunk_w(0,0,rt,2,2,sAb,w,lane); cpcommit();

    const int grow0 = rt*64 + w*16 + (lane>>2);
    const int cb = ct*16 + 2*(lane&3);
    const int klb = (ct&1)*16 + 2*(lane&3);
    const int rowl0 = w*16 + (lane>>2);

    for(int t=0; t<S_LEN; ++t){
        const int par = t&1;
        float accR0[8], accR1[8], accZ0[8], accZ1[8];
        float accI0[8], accI1[8], accH0[8], accH1[8];
#pragma unroll
        for(int i=0;i<8;i++){
            accR0[i]=0.f; accR1[i]=0.f; accZ0[i]=0.f; accZ1[i]=0.f;
            accI0[i]=0.f; accI1[i]=0.f; accH0[i]=0.f; accH1[i]=0.f;
        }

        // x chunks 0..7 -> accI ; barrier-free: per-warp wait + syncwarp only
        for(int kc=0; kc<8; ++kc){
            cpwait2(); __syncwarp();
            issue_chunk_w(t,par,rt,kc+3,(kc+3)&3,sAb,w,lane); cpcommit();
            unsigned aAddr = sAb + (unsigned)((kc&3)*SA_STAGE) + (unsigned)(w*1280) + laneoff;
            compute_kc(sWb, aAddr, kc, laneoff, accR0,accR1, accZ0,accZ1, accI0,accI1);
        }
        // h chunks 8..23 -> accH
        for(int kc=8; kc<24; ++kc){
            if(kc<22){ cpwait2(); } else if(kc==22){ cpwait1(); } else { cpwait0(); }
            __syncwarp();
            if(kc<21){ issue_chunk_w(t,par,rt,kc+3,(kc+3)&3,sAb,w,lane); cpcommit(); }
            unsigned aAddr = sAb + (unsigned)((kc&3)*SA_STAGE) + (unsigned)(w*1280) + laneoff;
            compute_kc(sWb, aAddr, kc, laneoff, accR0,accR1, accZ0,accZ1, accH0,accH1);
        }

        // ---- fused gate epilogue (R12-verified mapping; merge hi/lo terms here) ----
        const float* hprevB = d_h[par];
        float* houtB = d_h[par^1];
        const size_t imgB = (((size_t)(par^1)*4 + rt)*16 + (ct>>1))*2048;
#pragma unroll
        for(int nb=0; nb<2; nb++)
#pragma unroll
        for(int rh=0; rh<2; rh++){
            int f = nb*4 + rh*2;
            int grow = grow0 + rh*8;
            int gcol = cb + nb*8;
            float2 hp = *(const float2*)&hprevB[(size_t)grow*512 + gcol];
            float aR0 = accR0[f]+accR1[f],   aR1 = accR0[f+1]+accR1[f+1];
            float aZ0 = accZ0[f]+accZ1[f],   aZ1 = accZ0[f+1]+accZ1[f+1];
            float aI0 = accI0[f]+accI1[f],   aI1 = accI0[f+1]+accI1[f+1];
            float aH0 = accH0[f]+accH1[f],   aH1 = accH0[f+1]+accH1[f+1];
            float r0 = sigm(aR0), r1 = sigm(aR1);
            float z0 = sigm(aZ0), z1 = sigm(aZ1);
            float n0 = tanhf(aI0 + r0*aH0);
            float n1 = tanhf(aI1 + r1*aH1);
            float h0 = (1.f-z0)*n0 + z0*hp.x;
            float h1 = (1.f-z1)*n1 + z1*hp.y;
            *(float2*)&houtB[(size_t)grow*512 + gcol] = make_float2(h0,h1);
            __nv_bfloat16 bh0=__float2bfloat16(h0), bh1=__float2bfloat16(h1);
            *(unsigned*)&d_hbf[imgB + (size_t)(rowl0 + rh*8)*32 + klb + nb*8] =
                (unsigned)*(unsigned short*)&bh0 | ((unsigned)*(unsigned short*)&bh1 << 16);
        }

        // pre-issue next step's x chunks (0..2) — independent of h
        if(t+1 < S_LEN){
            issue_chunk_w(t+1,par^1,rt,0,0,sAb,w,lane); cpcommit();
            issue_chunk_w(t+1,par^1,rt,1,1,sAb,w,lane); cpcommit();
            issue_chunk_w(t+1,par^1,rt,2,2,sAb,w,lane); cpcommit();
        }
        grid_barrier((unsigned)(t+1));
    }
}

// ---------------- tail: generic tiled GEMM ----------------
template <int TRANSB>
__global__ __launch_bounds__(128) void gemm_tile_kernel(
        const float* __restrict__ A, int lda, const float* __restrict__ Bm, int ldb,
        float* __restrict__ C, int ldc, int K, int colTiles){
    int bid=blockIdx.x, rt=bid/colTiles, ct=bid%colTiles;
    int row0=rt*32, col0=ct*64;
    __shared__ __align__(16) float sA[16][36];
    __shared__ __align__(16) float sB[16][68];
    int tid=threadIdx.x, tr=tid>>4, tc=tid&15;
    float acc[4][4];
#pragma unroll
    for(int i=0;i<4;i++)
#pragma unroll
        for(int j=0;j<4;j++) acc[i][j]=0.f;
    for(int kk0=0;kk0<K;kk0+=16){
#pragma unroll
        for(int it=0;it<4;it++){ int idx=tid+it*128; int k=idx&15, r=idx>>4;
            sA[k][r]=A[(size_t)(row0+r)*lda+kk0+k]; }
        if(TRANSB){
#pragma unroll
            for(int it=0;it<8;it++){ int idx=tid+it*128; int k=idx&15, j=idx>>4;
                sB[k][j]=Bm[(size_t)(col0+j)*ldb+kk0+k]; }
        } else {
#pragma unroll
            for(int it=0;it<8;it++){ int idx=tid+it*128; int j=idx&63, k=idx>>6;
                sB[k][j]=Bm[(size_t)(kk0+k)*ldb+col0+j]; }
        }
        __syncthreads();
#pragma unroll
        for(int k=0;k<16;k++){
            float4 av=*(const float4*)&sA[k][tr<<2];
            float4 bv=*(const float4*)&sB[k][tc<<2];
            float a[4]={av.x,av.y,av.z,av.w}, b[4]={bv.x,bv.y,bv.z,bv.w};
#pragma unroll
            for(int i=0;i<4;i++)
#pragma unroll
                for(int j=0;j<4;j++) acc[i][j]+=a[i]*b[j];
        }
        __syncthreads();
    }
#pragma unroll
    for(int i=0;i<4;i++){
        float4 v=make_float4(acc[i][0],acc[i][1],acc[i][2],acc[i][3]);
        *(float4*)&C[(size_t)(row0+(tr<<2)+i)*ldc+col0+(tc<<2)]=v;
    }
}

__global__ __launch_bounds__(256) void softmax_kernel(){
    int b=blockIdx.x;
    const float* L=d_g+(size_t)b*HIST; float* A=d_alpha+(size_t)b*HIST;
    __shared__ float red[256];
    int tid=threadIdx.x;
    float m=-1e30f;
    for(int j=tid;j<HIST;j+=256) m=fmaxf(m,L[j]);
    red[tid]=m; __syncthreads();
    for(int s=128;s>0;s>>=1){ if(tid<s) red[tid]=fmaxf(red[tid],red[tid+s]); __syncthreads(); }
    m=red[0]; __syncthreads();
    float sum=0.f;
    for(int j=tid;j<HIST;j+=256){ float e=expf(L[j]-m); A[j]=e; sum+=e; }
    red[tid]=sum; __syncthreads();
    for(int s=128;s>0;s>>=1){ if(tid<s) red[tid]+=red[tid+s]; __syncthreads(); }
    float inv=1.f/red[0];
    for(int j=tid;j<HIST;j+=256) A[j]*=inv;
}
__global__ __launch_bounds__(256) void sigma_kernel(){
    int b=blockIdx.x, d=threadIdx.x;
    float t=d_sig[(size_t)b*DIN+d];
    d_inv_sigma[(size_t)b*DIN+d]=expf(-t);
    __shared__ float red[256];
    red[d]=t; __syncthreads();
    for(int s=128;s>0;s>>=1){ if(d<s) red[d]+=red[d+s]; __syncthreads(); }
    if(d==0) d_logdet[b]=red[0];
}
__global__ __launch_bounds__(256) void logprob_kernel(
        const float* __restrict__ x, float* __restrict__ out){
    int w=(blockIdx.x<<3)+(threadIdx.x>>5);
    int lane=threadIdx.x&31, b=w&255;
    const float4* xr=(const float4*)(x+((size_t)w<<8));
    const float4* mu=(const float4*)(d_mu+((size_t)b<<8));
    const float4* iv=(const float4*)(d_inv_sigma+((size_t)b<<8));
    float acc=0.f;
#pragma unroll
    for(int c=0;c<2;c++){
        int idx=lane+(c<<5);
        float4 xv=xr[idx], mv=mu[idx], sv=iv[idx];
        float d0=(xv.x-mv.x)*sv.x, d1=(xv.y-mv.y)*sv.y;
        float d2=(xv.z-mv.z)*sv.z, d3=(xv.w-mv.w)*sv.w;
        acc+=d0*d0+d1*d1+d2*d2+d3*d3;
    }
#pragma unroll
    for(int o=16;o;o>>=1) acc+=__shfl_xor_sync(0xffffffffu,acc,o);
    if(lane==0){
        const float log2pi=1.8378770664093453f;
        out[w]=-0.5f*(acc+256.0f*log2pi)-d_logdet[b];
    }
}

// ---------------- launch ----------------
extern "C" void kernel_launch(void* const* d_in, const int* in_sizes, int n_in,
                              void* d_out, int out_size){
    const float* x        = (const float*)d_in[0];
    const float* hidden   = (const float*)d_in[1];
    const float* external = (const float*)d_in[2];
    const float* w_ih     = (const float*)d_in[3];
    const float* w_hh     = (const float*)d_in[4];
    const float* w_alpha  = (const float*)d_in[5];
    const float* w_sigma  = (const float*)d_in[6];
    float* out = (float*)d_out;

    float *pH0, *pG, *pSig, *pAlpha, *pMu;
    cudaGetSymbolAddress((void**)&pH0, d_h);
    cudaGetSymbolAddress((void**)&pG, d_g);
    cudaGetSymbolAddress((void**)&pSig, d_sig);
    cudaGetSymbolAddress((void**)&pAlpha, d_alpha);
    cudaGetSymbolAddress((void**)&pMu, d_mu);

    cudaFuncSetAttribute(gru_hmma, cudaFuncAttributeMaxDynamicSharedMemorySize, SMEM_DYN);

    reset_barrier_kernel<<<1,1>>>();
    pack_x_kernel<<<131072,256>>>(x);
    pack_w_kernel<<<4608,256>>>(w_ih, w_hh);
    pack_h0_kernel<<<512,256>>>(hidden);

    gru_hmma<<<NB,128,SMEM_DYN>>>();        // final h lands in d_h[0]

    gemm_tile_kernel<1><<<8*32,128>>>(pH0, HID, w_alpha, HID, pG, HIST, HID, 32);
    softmax_kernel<<<BATCH,256>>>();
    gemm_tile_kernel<1><<<8*4,128>>>(pH0, HID, w_sigma, HID, pSig, DIN, HID, 4);
    sigma_kernel<<<BATCH,256>>>();
    gemm_tile_kernel<0><<<8*4,128>>>(pAlpha, HIST, external, DIN, pMu, DIN, HIST, 4);
    logprob_kernel<<<(S_LEN*BATCH)/8,256>>>(x, out);
}